// round 1
// baseline (speedup 1.0000x reference)
#include <cuda_runtime.h>
#include <cuda_bf16.h>
#include <math.h>

// Problem constants
#define D_MODEL 1024
#define N_HEADS 16
#define D_K     64
#define BATCH   4
#define SEQLEN  2048
#define M_ROWS  (BATCH * SEQLEN)   // 8192

// ---------------- scratch (device globals; no allocs allowed) ----------------
__device__ float g_q[(size_t)BATCH * N_HEADS * SEQLEN * D_K];   // (B*H, L, DK)
__device__ float g_k[(size_t)BATCH * N_HEADS * SEQLEN * D_K];
__device__ float g_v[(size_t)BATCH * N_HEADS * SEQLEN * D_K];
__device__ float g_att[(size_t)M_ROWS * D_MODEL];               // (B, L, D)

// ---------------- GEMM: C = A @ W^T + bias ----------------
// A: [M, K] row-major. W: [N, K] row-major. bias: [N].
// REMAP=true: write C[m,n] to (B,H,L,DK) layout; else plain [M,N].
#define BM 128
#define BN 128
#define BK 8
#define TM 8
#define TN 8

template <bool REMAP>
__global__ __launch_bounds__(256) void gemm_bias_kernel(
    const float* __restrict__ A, const float* __restrict__ W,
    const float* __restrict__ bias, float* __restrict__ C,
    int M, int N, int K)
{
    __shared__ float As[BK][BM];
    __shared__ float Bs[BK][BN];

    const int bc = blockIdx.x;   // along N
    const int br = blockIdx.y;   // along M
    const int tid = threadIdx.x;
    const int tr = tid >> 4;     // 0..15
    const int tc = tid & 15;     // 0..15

    const int ldRow  = tid >> 1; // 0..127
    const int ldHalf = tid & 1;  // which float4 of the 8-wide k slab

    const float* Aptr = A + (size_t)(br * BM + ldRow) * K + ldHalf * 4;
    const float* Wptr = W + (size_t)(bc * BN + ldRow) * K + ldHalf * 4;

    float acc[TM][TN];
#pragma unroll
    for (int i = 0; i < TM; i++)
#pragma unroll
        for (int j = 0; j < TN; j++) acc[i][j] = 0.0f;

    for (int k0 = 0; k0 < K; k0 += BK) {
        float4 av = *(const float4*)(Aptr + k0);
        float4 wv = *(const float4*)(Wptr + k0);
        As[ldHalf * 4 + 0][ldRow] = av.x;
        As[ldHalf * 4 + 1][ldRow] = av.y;
        As[ldHalf * 4 + 2][ldRow] = av.z;
        As[ldHalf * 4 + 3][ldRow] = av.w;
        Bs[ldHalf * 4 + 0][ldRow] = wv.x;
        Bs[ldHalf * 4 + 1][ldRow] = wv.y;
        Bs[ldHalf * 4 + 2][ldRow] = wv.z;
        Bs[ldHalf * 4 + 3][ldRow] = wv.w;
        __syncthreads();

#pragma unroll
        for (int k = 0; k < BK; k++) {
            float regM[TM], regN[TN];
#pragma unroll
            for (int i = 0; i < TM; i++) regM[i] = As[k][tr * TM + i];
#pragma unroll
            for (int j = 0; j < TN; j++) regN[j] = Bs[k][tc * TN + j];
#pragma unroll
            for (int i = 0; i < TM; i++)
#pragma unroll
                for (int j = 0; j < TN; j++)
                    acc[i][j] = fmaf(regM[i], regN[j], acc[i][j]);
        }
        __syncthreads();
    }

#pragma unroll
    for (int i = 0; i < TM; i++) {
        const int m = br * BM + tr * TM + i;
#pragma unroll
        for (int j = 0; j < TN; j++) {
            const int n = bc * BN + tc * TN + j;
            const float v = acc[i][j] + bias[n];
            if (REMAP) {
                const int b  = m >> 11;        // m / 2048
                const int l  = m & 2047;
                const int h  = n >> 6;         // n / 64
                const int dk = n & 63;
                C[((((size_t)b * N_HEADS + h) * SEQLEN) + l) * D_K + dk] = v;
            } else {
                C[(size_t)m * N + n] = v;
            }
        }
    }
}

// ---------------- Flash attention (fp32, causal) ----------------
// grid: (L/QT, B*H). 1 thread = 1 query row. q and o held in registers.
#define QT 128   // query rows per block (== threads)
#define TS 64    // kv tile rows in smem
#define CH 16    // score chunk held in registers

__global__ __launch_bounds__(QT) void flash_attn_kernel()
{
    __shared__ float Ks[TS][D_K];
    __shared__ float Vs[TS][D_K];

    const int bh  = blockIdx.y;            // 0..63
    const int qt  = blockIdx.x;            // 0..15
    const int t   = threadIdx.x;           // 0..127
    const int row = qt * QT + t;           // query position in [0, L)

    const float* qptr = g_q + ((size_t)bh * SEQLEN + row) * D_K;
    float4 q[D_K / 4];
#pragma unroll
    for (int i = 0; i < D_K / 4; i++) q[i] = ((const float4*)qptr)[i];

    float4 o[D_K / 4];
#pragma unroll
    for (int i = 0; i < D_K / 4; i++) o[i] = make_float4(0.f, 0.f, 0.f, 0.f);
    float m = -INFINITY;
    float l = 0.0f;

    const float scale = 0.125f;            // 1/sqrt(64)
    const int kv_end = (qt + 1) * QT;      // causal: only tiles touching <= row_max

    for (int kb = 0; kb < kv_end; kb += TS) {
        // cooperative load of K,V tiles: TS*64 floats = 1024 float4, 128 threads
        const float4* ksrc = (const float4*)(g_k + ((size_t)bh * SEQLEN + kb) * D_K);
        const float4* vsrc = (const float4*)(g_v + ((size_t)bh * SEQLEN + kb) * D_K);
#pragma unroll
        for (int u = 0; u < 8; u++) {
            const int idx = u * QT + t;    // 0..1023
            ((float4*)Ks)[idx] = ksrc[idx];
            ((float4*)Vs)[idx] = vsrc[idx];
        }
        __syncthreads();

        for (int jc = 0; jc < TS; jc += CH) {
            float s[CH];
            float smax = -INFINITY;
#pragma unroll
            for (int jj = 0; jj < CH; jj++) {
                const int j = jc + jj;
                const float4* kr = (const float4*)Ks[j];
                float a0 = 0.f, a1 = 0.f, a2 = 0.f, a3 = 0.f;
#pragma unroll
                for (int i = 0; i < D_K / 4; i++) {
                    float4 kv = kr[i];
                    a0 = fmaf(q[i].x, kv.x, a0);
                    a1 = fmaf(q[i].y, kv.y, a1);
                    a2 = fmaf(q[i].z, kv.z, a2);
                    a3 = fmaf(q[i].w, kv.w, a3);
                }
                float sc = (a0 + a1) + (a2 + a3);
                sc *= scale;
                s[jj] = (kb + j <= row) ? sc : -INFINITY;
                smax = fmaxf(smax, s[jj]);
            }
            const float newm = fmaxf(m, smax);
            if (newm != -INFINITY) {
                const float corr = __expf(m - newm);   // m=-inf -> 0
                m = newm;
                l *= corr;
#pragma unroll
                for (int i = 0; i < D_K / 4; i++) {
                    o[i].x *= corr; o[i].y *= corr; o[i].z *= corr; o[i].w *= corr;
                }
#pragma unroll
                for (int jj = 0; jj < CH; jj++) {
                    const float p = __expf(s[jj] - m);
                    l += p;
                    const float4* vr = (const float4*)Vs[jc + jj];
#pragma unroll
                    for (int i = 0; i < D_K / 4; i++) {
                        float4 vv = vr[i];
                        o[i].x = fmaf(p, vv.x, o[i].x);
                        o[i].y = fmaf(p, vv.y, o[i].y);
                        o[i].z = fmaf(p, vv.z, o[i].z);
                        o[i].w = fmaf(p, vv.w, o[i].w);
                    }
                }
            }
        }
        __syncthreads();
    }

    const float inv = 1.0f / l;
    const int b = bh >> 4;      // bh / 16
    const int h = bh & 15;
    float4* optr = (float4*)(g_att + ((size_t)b * SEQLEN + row) * D_MODEL + h * D_K);
#pragma unroll
    for (int i = 0; i < D_K / 4; i++) {
        float4 v = o[i];
        v.x *= inv; v.y *= inv; v.z *= inv; v.w *= inv;
        optr[i] = v;
    }
}

// ---------------- launcher ----------------
extern "C" void kernel_launch(void* const* d_in, const int* in_sizes, int n_in,
                              void* d_out, int out_size)
{
    const float* Q  = (const float*)d_in[0];
    const float* K  = (const float*)d_in[1];
    const float* V  = (const float*)d_in[2];
    // d_in[3] = attn_mask (tril, causal) — implemented implicitly
    const float* Wq = (const float*)d_in[4];
    const float* bq = (const float*)d_in[5];
    const float* Wk = (const float*)d_in[6];
    const float* bk = (const float*)d_in[7];
    const float* Wv = (const float*)d_in[8];
    const float* bv = (const float*)d_in[9];
    const float* Wo = (const float*)d_in[10];
    const float* bo = (const float*)d_in[11];
    float* out = (float*)d_out;

    float *pq, *pk, *pv, *patt;
    cudaGetSymbolAddress((void**)&pq,  g_q);
    cudaGetSymbolAddress((void**)&pk,  g_k);
    cudaGetSymbolAddress((void**)&pv,  g_v);
    cudaGetSymbolAddress((void**)&patt, g_att);

    dim3 gemm_grid(D_MODEL / BN, M_ROWS / BM);   // (8, 64)
    dim3 gemm_block(256);

    gemm_bias_kernel<true><<<gemm_grid, gemm_block>>>(Q, Wq, bq, pq, M_ROWS, D_MODEL, D_MODEL);
    gemm_bias_kernel<true><<<gemm_grid, gemm_block>>>(K, Wk, bk, pk, M_ROWS, D_MODEL, D_MODEL);
    gemm_bias_kernel<true><<<gemm_grid, gemm_block>>>(V, Wv, bv, pv, M_ROWS, D_MODEL, D_MODEL);

    dim3 attn_grid(SEQLEN / QT, BATCH * N_HEADS); // (16, 64)
    flash_attn_kernel<<<attn_grid, QT>>>();

    gemm_bias_kernel<false><<<gemm_grid, gemm_block>>>(patt, Wo, bo, out, M_ROWS, D_MODEL, D_MODEL);
}

// round 6
// speedup vs baseline: 1.4963x; 1.4963x over previous
#include <cuda_runtime.h>
#include <cuda_bf16.h>
#include <math.h>
#include <stdint.h>

// Problem constants
#define D_MODEL 1024
#define N_HEADS 16
#define D_K     64
#define BATCH   4
#define SEQLEN  2048
#define M_ROWS  (BATCH * SEQLEN)   // 8192

// ---------------- scratch (device globals; no allocs allowed) ----------------
__device__ float g_q[(size_t)BATCH * N_HEADS * SEQLEN * D_K];   // (B*H, L, DK)
__device__ float g_k[(size_t)BATCH * N_HEADS * SEQLEN * D_K];
__device__ float g_v[(size_t)BATCH * N_HEADS * SEQLEN * D_K];
__device__ float g_att[(size_t)M_ROWS * D_MODEL];               // (B, L, D)

// ======================= helpers =======================
__device__ __forceinline__ uint32_t smem_u32(const void* p) {
    uint32_t a;
    asm("{ .reg .u64 t; cvta.to.shared.u64 t, %1; cvt.u32.u64 %0, t; }"
        : "=r"(a) : "l"(p));
    return a;
}

__device__ __forceinline__ void ldmx4(uint32_t* r, uint32_t addr) {
    asm volatile("ldmatrix.sync.aligned.m8n8.x4.shared.b16 {%0,%1,%2,%3}, [%4];"
                 : "=r"(r[0]), "=r"(r[1]), "=r"(r[2]), "=r"(r[3]) : "r"(addr));
}

__device__ __forceinline__ void mma_bf16(float* c, const uint32_t* a, const uint32_t* b) {
    asm volatile(
        "mma.sync.aligned.m16n8k16.row.col.f32.bf16.bf16.f32 "
        "{%0,%1,%2,%3}, {%4,%5,%6,%7}, {%8,%9}, {%0,%1,%2,%3};"
        : "+f"(c[0]), "+f"(c[1]), "+f"(c[2]), "+f"(c[3])
        : "r"(a[0]), "r"(a[1]), "r"(a[2]), "r"(a[3]), "r"(b[0]), "r"(b[1]));
}

// split fp32 -> bf16 hi + bf16 lo (packed pairs)
__device__ __forceinline__ uint32_t split_pair(float a, float b, uint32_t& lo_out) {
    __nv_bfloat16 ha = __float2bfloat16(a);
    __nv_bfloat16 hb = __float2bfloat16(b);
    float ra = a - __bfloat162float(ha);
    float rb = b - __bfloat162float(hb);
    __nv_bfloat16 la = __float2bfloat16(ra);
    __nv_bfloat16 lb = __float2bfloat16(rb);
    lo_out = (uint32_t)__bfloat16_as_ushort(la) | ((uint32_t)__bfloat16_as_ushort(lb) << 16);
    return (uint32_t)__bfloat16_as_ushort(ha) | ((uint32_t)__bfloat16_as_ushort(hb) << 16);
}

// ============== mma.sync GEMM: C = A @ W^T + bias (split-bf16, 3 terms) ==============
// A: [M,1024] fp32 row-major, W: [N=1024,1024] fp32 row-major.
// CTA tile 128x128, 8 warps (4 along M x 2 along N), warp tile 32x64, BK=32.
// Both A and W are K-contiguous -> BOTH use non-trans ldmatrix for row.col mma.
#define GBM 128
#define GBN 128
#define GBK 32
#define NKT (D_MODEL / GBK)          // 32
#define ROWB 80                      // smem row stride in bytes (32 bf16 + 8 pad)

template <bool REMAP>
__global__ __launch_bounds__(256, 2) void gemm_mma_kernel(
    const float* __restrict__ A, const float* __restrict__ W,
    const float* __restrict__ bias, float* __restrict__ C)
{
    __shared__ __align__(16) char sAh[GBM * ROWB];
    __shared__ __align__(16) char sAl[GBM * ROWB];
    __shared__ __align__(16) char sWh[GBN * ROWB];
    __shared__ __align__(16) char sWl[GBN * ROWB];

    const int tid  = threadIdx.x;
    const int wid  = tid >> 5;
    const int lane = tid & 31;
    const int warp_m = wid & 3;       // 0..3 -> m base warp_m*32
    const int warp_n = wid >> 2;      // 0..1 -> n base warp_n*64

    // ---- global load assignment: thread -> (row, 16-col half) ----
    const int ldrow  = tid >> 1;      // 0..127
    const int ldhalf = tid & 1;       // 0..1
    const float4* gA = (const float4*)(A + (size_t)(blockIdx.y * GBM + ldrow) * D_MODEL + ldhalf * 16);
    const float4* gW = (const float4*)(W + (size_t)(blockIdx.x * GBN + ldrow) * D_MODEL + ldhalf * 16);
    const uint32_t st = (uint32_t)(ldrow * ROWB + ldhalf * 32);

    const uint32_t aAh = smem_u32(sAh), aAl = smem_u32(sAl);
    const uint32_t aWh = smem_u32(sWh), aWl = smem_u32(sWl);

    // ---- ldmatrix per-thread address components ----
    const int g = lane >> 3;                 // 0..3
    // A: matrices a0..a3 = (m0-7,k0),(m8-15,k0),(m0-7,k8),(m8-15,k8)
    const int ra = warp_m * 32 + (g & 1) * 8 + (lane & 7);
    const int ka = (g >> 1) * 16;            // byte offset within kstep
    // B (non-trans on [n][k] tile): matrices b0..b3 = (n0-7,k0),(n0-7,k8),(n8-15,k0),(n8-15,k8)
    const int rb = warp_n * 64 + (g >> 1) * 8 + (lane & 7);
    const int kb = (g & 1) * 16;

    float acc[2][8][4];
#pragma unroll
    for (int i = 0; i < 2; i++)
#pragma unroll
        for (int j = 0; j < 8; j++)
#pragma unroll
            for (int k = 0; k < 4; k++) acc[i][j][k] = 0.0f;

    for (int kt = 0; kt < NKT; kt++) {
        // ---- load + split tiles into smem ----
        {
            float4 f0 = gA[kt * 8 + 0], f1 = gA[kt * 8 + 1], f2 = gA[kt * 8 + 2], f3 = gA[kt * 8 + 3];
            uint32_t h[8], l[8];
            h[0] = split_pair(f0.x, f0.y, l[0]);
            h[1] = split_pair(f0.z, f0.w, l[1]);
            h[2] = split_pair(f1.x, f1.y, l[2]);
            h[3] = split_pair(f1.z, f1.w, l[3]);
            h[4] = split_pair(f2.x, f2.y, l[4]);
            h[5] = split_pair(f2.z, f2.w, l[5]);
            h[6] = split_pair(f3.x, f3.y, l[6]);
            h[7] = split_pair(f3.z, f3.w, l[7]);
            *(uint4*)(sAh + st)      = make_uint4(h[0], h[1], h[2], h[3]);
            *(uint4*)(sAh + st + 16) = make_uint4(h[4], h[5], h[6], h[7]);
            *(uint4*)(sAl + st)      = make_uint4(l[0], l[1], l[2], l[3]);
            *(uint4*)(sAl + st + 16) = make_uint4(l[4], l[5], l[6], l[7]);
        }
        {
            float4 f0 = gW[kt * 8 + 0], f1 = gW[kt * 8 + 1], f2 = gW[kt * 8 + 2], f3 = gW[kt * 8 + 3];
            uint32_t h[8], l[8];
            h[0] = split_pair(f0.x, f0.y, l[0]);
            h[1] = split_pair(f0.z, f0.w, l[1]);
            h[2] = split_pair(f1.x, f1.y, l[2]);
            h[3] = split_pair(f1.z, f1.w, l[3]);
            h[4] = split_pair(f2.x, f2.y, l[4]);
            h[5] = split_pair(f2.z, f2.w, l[5]);
            h[6] = split_pair(f3.x, f3.y, l[6]);
            h[7] = split_pair(f3.z, f3.w, l[7]);
            *(uint4*)(sWh + st)      = make_uint4(h[0], h[1], h[2], h[3]);
            *(uint4*)(sWh + st + 16) = make_uint4(h[4], h[5], h[6], h[7]);
            *(uint4*)(sWl + st)      = make_uint4(l[0], l[1], l[2], l[3]);
            *(uint4*)(sWl + st + 16) = make_uint4(l[4], l[5], l[6], l[7]);
        }
        __syncthreads();

        // ---- MMA phase: 2 ksteps of 16 ----
#pragma unroll
        for (int ks = 0; ks < 2; ks++) {
            uint32_t ah[2][4], al[2][4];
#pragma unroll
            for (int mc = 0; mc < 2; mc++) {
                const uint32_t arow = (uint32_t)((ra + mc * 16) * ROWB + ks * 32 + ka);
                ldmx4(ah[mc], aAh + arow);
                ldmx4(al[mc], aAl + arow);
            }
            // W_hi terms: A_hi*W_hi + A_lo*W_hi
#pragma unroll
            for (int ncp = 0; ncp < 4; ncp++) {
                uint32_t b[4];
                ldmx4(b, aWh + (uint32_t)((rb + ncp * 16) * ROWB + ks * 32 + kb));
#pragma unroll
                for (int mc = 0; mc < 2; mc++) {
                    mma_bf16(acc[mc][ncp * 2 + 0], ah[mc], b);
                    mma_bf16(acc[mc][ncp * 2 + 1], ah[mc], b + 2);
                    mma_bf16(acc[mc][ncp * 2 + 0], al[mc], b);
                    mma_bf16(acc[mc][ncp * 2 + 1], al[mc], b + 2);
                }
            }
            // W_lo term: A_hi*W_lo
#pragma unroll
            for (int ncp = 0; ncp < 4; ncp++) {
                uint32_t b[4];
                ldmx4(b, aWl + (uint32_t)((rb + ncp * 16) * ROWB + ks * 32 + kb));
#pragma unroll
                for (int mc = 0; mc < 2; mc++) {
                    mma_bf16(acc[mc][ncp * 2 + 0], ah[mc], b);
                    mma_bf16(acc[mc][ncp * 2 + 1], ah[mc], b + 2);
                }
            }
        }
        __syncthreads();
    }

    // ---- epilogue: bias + store ----
    const int r0 = blockIdx.y * GBM + warp_m * 32 + (lane >> 2);
    const int c0 = blockIdx.x * GBN + warp_n * 64 + (lane & 3) * 2;
#pragma unroll
    for (int mc = 0; mc < 2; mc++) {
#pragma unroll
        for (int nc = 0; nc < 8; nc++) {
            const int n = c0 + nc * 8;
            const float2 bv = *(const float2*)(bias + n);
#pragma unroll
            for (int h2 = 0; h2 < 2; h2++) {
                const int m = r0 + mc * 16 + h2 * 8;
                float2 v;
                v.x = acc[mc][nc][h2 * 2 + 0] + bv.x;
                v.y = acc[mc][nc][h2 * 2 + 1] + bv.y;
                if (REMAP) {
                    const int b  = m >> 11;
                    const int l  = m & 2047;
                    const int hd = n >> 6;
                    const int dk = n & 63;
                    *(float2*)(C + ((((size_t)b * N_HEADS + hd) * SEQLEN) + l) * D_K + dk) = v;
                } else {
                    *(float2*)(C + (size_t)m * D_MODEL + n) = v;
                }
            }
        }
    }
}

// ---------------- Flash attention (fp32, causal) — unchanged ----------------
#define QT 128
#define TS 64
#define CH 16

__global__ __launch_bounds__(QT) void flash_attn_kernel()
{
    __shared__ float Ks[TS][D_K];
    __shared__ float Vs[TS][D_K];

    const int bh  = blockIdx.y;
    const int qt  = blockIdx.x;
    const int t   = threadIdx.x;
    const int row = qt * QT + t;

    const float* qptr = g_q + ((size_t)bh * SEQLEN + row) * D_K;
    float4 q[D_K / 4];
#pragma unroll
    for (int i = 0; i < D_K / 4; i++) q[i] = ((const float4*)qptr)[i];

    float4 o[D_K / 4];
#pragma unroll
    for (int i = 0; i < D_K / 4; i++) o[i] = make_float4(0.f, 0.f, 0.f, 0.f);
    float m = -INFINITY;
    float l = 0.0f;

    const float scale = 0.125f;
    const int kv_end = (qt + 1) * QT;

    for (int kb = 0; kb < kv_end; kb += TS) {
        const float4* ksrc = (const float4*)(g_k + ((size_t)bh * SEQLEN + kb) * D_K);
        const float4* vsrc = (const float4*)(g_v + ((size_t)bh * SEQLEN + kb) * D_K);
#pragma unroll
        for (int u = 0; u < 8; u++) {
            const int idx = u * QT + t;
            ((float4*)Ks)[idx] = ksrc[idx];
            ((float4*)Vs)[idx] = vsrc[idx];
        }
        __syncthreads();

        for (int jc = 0; jc < TS; jc += CH) {
            float s[CH];
            float smax = -INFINITY;
#pragma unroll
            for (int jj = 0; jj < CH; jj++) {
                const int j = jc + jj;
                const float4* kr = (const float4*)Ks[j];
                float a0 = 0.f, a1 = 0.f, a2 = 0.f, a3 = 0.f;
#pragma unroll
                for (int i = 0; i < D_K / 4; i++) {
                    float4 kv = kr[i];
                    a0 = fmaf(q[i].x, kv.x, a0);
                    a1 = fmaf(q[i].y, kv.y, a1);
                    a2 = fmaf(q[i].z, kv.z, a2);
                    a3 = fmaf(q[i].w, kv.w, a3);
                }
                float sc = (a0 + a1) + (a2 + a3);
                sc *= scale;
                s[jj] = (kb + j <= row) ? sc : -INFINITY;
                smax = fmaxf(smax, s[jj]);
            }
            const float newm = fmaxf(m, smax);
            if (newm != -INFINITY) {
                const float corr = __expf(m - newm);
                m = newm;
                l *= corr;
#pragma unroll
                for (int i = 0; i < D_K / 4; i++) {
                    o[i].x *= corr; o[i].y *= corr; o[i].z *= corr; o[i].w *= corr;
                }
#pragma unroll
                for (int jj = 0; jj < CH; jj++) {
                    const float p = __expf(s[jj] - m);
                    l += p;
                    const float4* vr = (const float4*)Vs[jc + jj];
#pragma unroll
                    for (int i = 0; i < D_K / 4; i++) {
                        float4 vv = vr[i];
                        o[i].x = fmaf(p, vv.x, o[i].x);
                        o[i].y = fmaf(p, vv.y, o[i].y);
                        o[i].z = fmaf(p, vv.z, o[i].z);
                        o[i].w = fmaf(p, vv.w, o[i].w);
                    }
                }
            }
        }
        __syncthreads();
    }

    const float inv = 1.0f / l;
    const int b = bh >> 4;
    const int h = bh & 15;
    float4* optr = (float4*)(g_att + ((size_t)b * SEQLEN + row) * D_MODEL + h * D_K);
#pragma unroll
    for (int i = 0; i < D_K / 4; i++) {
        float4 v = o[i];
        v.x *= inv; v.y *= inv; v.z *= inv; v.w *= inv;
        optr[i] = v;
    }
}

// ---------------- launcher ----------------
extern "C" void kernel_launch(void* const* d_in, const int* in_sizes, int n_in,
                              void* d_out, int out_size)
{
    const float* Q  = (const float*)d_in[0];
    const float* K  = (const float*)d_in[1];
    const float* V  = (const float*)d_in[2];
    // d_in[3] = attn_mask (tril) — implemented implicitly as causal
    const float* Wq = (const float*)d_in[4];
    const float* bq = (const float*)d_in[5];
    const float* Wk = (const float*)d_in[6];
    const float* bk = (const float*)d_in[7];
    const float* Wv = (const float*)d_in[8];
    const float* bv = (const float*)d_in[9];
    const float* Wo = (const float*)d_in[10];
    const float* bo = (const float*)d_in[11];
    float* out = (float*)d_out;

    float *pq, *pk, *pv, *patt;
    cudaGetSymbolAddress((void**)&pq,  g_q);
    cudaGetSymbolAddress((void**)&pk,  g_k);
    cudaGetSymbolAddress((void**)&pv,  g_v);
    cudaGetSymbolAddress((void**)&patt, g_att);

    dim3 ggrid(D_MODEL / GBN, M_ROWS / GBM);   // (8, 64)

    gemm_mma_kernel<true><<<ggrid, 256>>>(Q, Wq, bq, pq);
    gemm_mma_kernel<true><<<ggrid, 256>>>(K, Wk, bk, pk);
    gemm_mma_kernel<true><<<ggrid, 256>>>(V, Wv, bv, pv);

    dim3 attn_grid(SEQLEN / QT, BATCH * N_HEADS); // (16, 64)
    flash_attn_kernel<<<attn_grid, QT>>>();

    gemm_mma_kernel<false><<<ggrid, 256>>>(patt, Wo, bo, out);
}

// round 7
// speedup vs baseline: 1.5817x; 1.0570x over previous
#include <cuda_runtime.h>
#include <cuda_bf16.h>
#include <math.h>
#include <stdint.h>

// Problem constants
#define D_MODEL 1024
#define N_HEADS 16
#define D_K     64
#define BATCH   4
#define SEQLEN  2048
#define M_ROWS  (BATCH * SEQLEN)   // 8192

// ---------------- scratch (device globals; no allocs allowed) ----------------
__device__ float g_q[(size_t)BATCH * N_HEADS * SEQLEN * D_K];   // (B*H, L, DK) fp32
__device__ float g_k[(size_t)BATCH * N_HEADS * SEQLEN * D_K];
__device__ float g_v[(size_t)BATCH * N_HEADS * SEQLEN * D_K];

// pre-split bf16 operands
__device__ __nv_bfloat16 g_xqh[(size_t)M_ROWS * D_MODEL], g_xql[(size_t)M_ROWS * D_MODEL];
__device__ __nv_bfloat16 g_xkh[(size_t)M_ROWS * D_MODEL], g_xkl[(size_t)M_ROWS * D_MODEL];
__device__ __nv_bfloat16 g_xvh[(size_t)M_ROWS * D_MODEL], g_xvl[(size_t)M_ROWS * D_MODEL];
__device__ __nv_bfloat16 g_wqh[(size_t)D_MODEL * D_MODEL], g_wql[(size_t)D_MODEL * D_MODEL];
__device__ __nv_bfloat16 g_wkh[(size_t)D_MODEL * D_MODEL], g_wkl[(size_t)D_MODEL * D_MODEL];
__device__ __nv_bfloat16 g_wvh[(size_t)D_MODEL * D_MODEL], g_wvl[(size_t)D_MODEL * D_MODEL];
__device__ __nv_bfloat16 g_woh[(size_t)D_MODEL * D_MODEL], g_wol[(size_t)D_MODEL * D_MODEL];
__device__ __nv_bfloat16 g_atth[(size_t)M_ROWS * D_MODEL], g_attl[(size_t)M_ROWS * D_MODEL];

// ======================= helpers =======================
__device__ __forceinline__ uint32_t smem_u32(const void* p) {
    uint32_t a;
    asm("{ .reg .u64 t; cvta.to.shared.u64 t, %1; cvt.u32.u64 %0, t; }"
        : "=r"(a) : "l"(p));
    return a;
}

__device__ __forceinline__ void cp16(uint32_t dst, const void* src) {
    asm volatile("cp.async.cg.shared.global [%0], [%1], 16;" :: "r"(dst), "l"(src));
}
__device__ __forceinline__ void cp_commit() {
    asm volatile("cp.async.commit_group;" ::: "memory");
}
__device__ __forceinline__ void cp_wait0() {
    asm volatile("cp.async.wait_group 0;" ::: "memory");
}

__device__ __forceinline__ void ldmx4(uint32_t* r, uint32_t addr) {
    asm volatile("ldmatrix.sync.aligned.m8n8.x4.shared.b16 {%0,%1,%2,%3}, [%4];"
                 : "=r"(r[0]), "=r"(r[1]), "=r"(r[2]), "=r"(r[3]) : "r"(addr));
}

__device__ __forceinline__ void mma_bf16(float* c, const uint32_t* a, const uint32_t* b) {
    asm volatile(
        "mma.sync.aligned.m16n8k16.row.col.f32.bf16.bf16.f32 "
        "{%0,%1,%2,%3}, {%4,%5,%6,%7}, {%8,%9}, {%0,%1,%2,%3};"
        : "+f"(c[0]), "+f"(c[1]), "+f"(c[2]), "+f"(c[3])
        : "r"(a[0]), "r"(a[1]), "r"(a[2]), "r"(a[3]), "r"(b[0]), "r"(b[1]));
}

// split fp32 -> bf16 hi + bf16 lo (packed pairs)
__device__ __forceinline__ uint32_t split_pair(float a, float b, uint32_t& lo_out) {
    __nv_bfloat16 ha = __float2bfloat16(a);
    __nv_bfloat16 hb = __float2bfloat16(b);
    float ra = a - __bfloat162float(ha);
    float rb = b - __bfloat162float(hb);
    __nv_bfloat16 la = __float2bfloat16(ra);
    __nv_bfloat16 lb = __float2bfloat16(rb);
    lo_out = (uint32_t)__bfloat16_as_ushort(la) | ((uint32_t)__bfloat16_as_ushort(lb) << 16);
    return (uint32_t)__bfloat16_as_ushort(ha) | ((uint32_t)__bfloat16_as_ushort(hb) << 16);
}

// ---------------- split pass: fp32 -> (hi, lo) bf16 ----------------
__global__ __launch_bounds__(256) void split_kernel(
    const float4* __restrict__ src, __nv_bfloat16* __restrict__ hi,
    __nv_bfloat16* __restrict__ lo)
{
    const int i = blockIdx.x * 256 + threadIdx.x;
    const float4 f = src[i];
    uint32_t l0, l1;
    const uint32_t h0 = split_pair(f.x, f.y, l0);
    const uint32_t h1 = split_pair(f.z, f.w, l1);
    ((uint2*)hi)[i] = make_uint2(h0, h1);
    ((uint2*)lo)[i] = make_uint2(l0, l1);
}

// ============== mma.sync GEMM v2: C = A @ W^T + bias (pre-split bf16, cp.async) ==============
// A_hi/lo: [M,1024] bf16, W_hi/lo: [1024,1024] bf16, all K-contiguous.
// CTA tile 128x128, 8 warps (4 M x 2 N), warp tile 32x64, BK=32, double-buffered.
#define GBM 128
#define GBN 128
#define GBK 32
#define NKT (D_MODEL / GBK)          // 32
#define ROWB 80                      // smem row stride (32 bf16 = 64B + 16B pad)
#define SBUF (128 * ROWB)            // 10240 B per tile array
#define SM_TOT (2 * 4 * SBUF)        // 81920 B

template <bool REMAP>
__global__ __launch_bounds__(256, 2) void gemm_bf16_kernel(
    const __nv_bfloat16* __restrict__ Ah, const __nv_bfloat16* __restrict__ Al,
    const __nv_bfloat16* __restrict__ Wh, const __nv_bfloat16* __restrict__ Wl,
    const float* __restrict__ bias, float* __restrict__ C)
{
    extern __shared__ __align__(16) char smem[];
    const uint32_t sb = smem_u32(smem);

    const int tid  = threadIdx.x;
    const int wid  = tid >> 5;
    const int lane = tid & 31;
    const int warp_m = wid & 3;
    const int warp_n = wid >> 2;

    const int aRow0 = blockIdx.y * GBM;
    const int wRow0 = blockIdx.x * GBN;

    // ---- ldmatrix per-thread address components (verified in round 6) ----
    const int g = lane >> 3;
    const int ra = warp_m * 32 + (g & 1) * 8 + (lane & 7);
    const int ka = (g >> 1) * 16;
    const int rb = warp_n * 64 + (g >> 1) * 8 + (lane & 7);
    const int kb = (g & 1) * 16;

    float acc[2][8][4];
#pragma unroll
    for (int i = 0; i < 2; i++)
#pragma unroll
        for (int j = 0; j < 8; j++)
#pragma unroll
            for (int k = 0; k < 4; k++) acc[i][j][k] = 0.0f;

    // ---- async tile loader: 512 16B-chunks per array, 2 per thread ----
    auto load_tiles = [&](uint32_t bufbase, int kt) {
#pragma unroll
        for (int u = 0; u < 2; u++) {
            const int c   = u * 256 + tid;
            const int row = c >> 2;
            const int c4  = c & 3;
            const size_t aoff = (size_t)(aRow0 + row) * D_MODEL + kt * GBK + c4 * 8;
            const size_t woff = (size_t)(wRow0 + row) * D_MODEL + kt * GBK + c4 * 8;
            const uint32_t d = (uint32_t)(row * ROWB + c4 * 16);
            cp16(bufbase + 0 * SBUF + d, Ah + aoff);
            cp16(bufbase + 1 * SBUF + d, Al + aoff);
            cp16(bufbase + 2 * SBUF + d, Wh + woff);
            cp16(bufbase + 3 * SBUF + d, Wl + woff);
        }
    };

    load_tiles(sb, 0);
    cp_commit();

    for (int kt = 0; kt < NKT; kt++) {
        cp_wait0();
        __syncthreads();

        if (kt + 1 < NKT) {
            load_tiles(sb + ((kt + 1) & 1) * 4 * SBUF, kt + 1);
            cp_commit();
        }

        const uint32_t base = sb + (kt & 1) * 4 * SBUF;
        const uint32_t bAh = base, bAl = base + SBUF, bWh = base + 2 * SBUF, bWl = base + 3 * SBUF;

#pragma unroll
        for (int ks = 0; ks < 2; ks++) {
            uint32_t ah[2][4], al[2][4];
#pragma unroll
            for (int mc = 0; mc < 2; mc++) {
                const uint32_t arow = (uint32_t)((ra + mc * 16) * ROWB + ks * 32 + ka);
                ldmx4(ah[mc], bAh + arow);
                ldmx4(al[mc], bAl + arow);
            }
            // W_hi terms: A_hi*W_hi + A_lo*W_hi
#pragma unroll
            for (int ncp = 0; ncp < 4; ncp++) {
                uint32_t b[4];
                ldmx4(b, bWh + (uint32_t)((rb + ncp * 16) * ROWB + ks * 32 + kb));
#pragma unroll
                for (int mc = 0; mc < 2; mc++) {
                    mma_bf16(acc[mc][ncp * 2 + 0], ah[mc], b);
                    mma_bf16(acc[mc][ncp * 2 + 1], ah[mc], b + 2);
                    mma_bf16(acc[mc][ncp * 2 + 0], al[mc], b);
                    mma_bf16(acc[mc][ncp * 2 + 1], al[mc], b + 2);
                }
            }
            // W_lo term: A_hi*W_lo
#pragma unroll
            for (int ncp = 0; ncp < 4; ncp++) {
                uint32_t b[4];
                ldmx4(b, bWl + (uint32_t)((rb + ncp * 16) * ROWB + ks * 32 + kb));
#pragma unroll
                for (int mc = 0; mc < 2; mc++) {
                    mma_bf16(acc[mc][ncp * 2 + 0], ah[mc], b);
                    mma_bf16(acc[mc][ncp * 2 + 1], ah[mc], b + 2);
                }
            }
        }
        __syncthreads();
    }

    // ---- epilogue: bias + store ----
    const int r0 = blockIdx.y * GBM + warp_m * 32 + (lane >> 2);
    const int c0 = blockIdx.x * GBN + warp_n * 64 + (lane & 3) * 2;
#pragma unroll
    for (int mc = 0; mc < 2; mc++) {
#pragma unroll
        for (int nc = 0; nc < 8; nc++) {
            const int n = c0 + nc * 8;
            const float2 bv = *(const float2*)(bias + n);
#pragma unroll
            for (int h2 = 0; h2 < 2; h2++) {
                const int m = r0 + mc * 16 + h2 * 8;
                float2 v;
                v.x = acc[mc][nc][h2 * 2 + 0] + bv.x;
                v.y = acc[mc][nc][h2 * 2 + 1] + bv.y;
                if (REMAP) {
                    const int b  = m >> 11;
                    const int l  = m & 2047;
                    const int hd = n >> 6;
                    const int dk = n & 63;
                    *(float2*)(C + ((((size_t)b * N_HEADS + hd) * SEQLEN) + l) * D_K + dk) = v;
                } else {
                    *(float2*)(C + (size_t)m * D_MODEL + n) = v;
                }
            }
        }
    }
}

// ---------------- Flash attention (fp32, causal); writes split bf16 output ----------------
#define QT 128
#define TS 64
#define CH 16

__global__ __launch_bounds__(QT) void flash_attn_kernel()
{
    __shared__ float Ks[TS][D_K];
    __shared__ float Vs[TS][D_K];

    const int bh  = blockIdx.y;
    const int qt  = blockIdx.x;
    const int t   = threadIdx.x;
    const int row = qt * QT + t;

    const float* qptr = g_q + ((size_t)bh * SEQLEN + row) * D_K;
    float4 q[D_K / 4];
#pragma unroll
    for (int i = 0; i < D_K / 4; i++) q[i] = ((const float4*)qptr)[i];

    float4 o[D_K / 4];
#pragma unroll
    for (int i = 0; i < D_K / 4; i++) o[i] = make_float4(0.f, 0.f, 0.f, 0.f);
    float m = -INFINITY;
    float l = 0.0f;

    const float scale = 0.125f;
    const int kv_end = (qt + 1) * QT;

    for (int kb = 0; kb < kv_end; kb += TS) {
        const float4* ksrc = (const float4*)(g_k + ((size_t)bh * SEQLEN + kb) * D_K);
        const float4* vsrc = (const float4*)(g_v + ((size_t)bh * SEQLEN + kb) * D_K);
#pragma unroll
        for (int u = 0; u < 8; u++) {
            const int idx = u * QT + t;
            ((float4*)Ks)[idx] = ksrc[idx];
            ((float4*)Vs)[idx] = vsrc[idx];
        }
        __syncthreads();

        for (int jc = 0; jc < TS; jc += CH) {
            float s[CH];
            float smax = -INFINITY;
#pragma unroll
            for (int jj = 0; jj < CH; jj++) {
                const int j = jc + jj;
                const float4* kr = (const float4*)Ks[j];
                float a0 = 0.f, a1 = 0.f, a2 = 0.f, a3 = 0.f;
#pragma unroll
                for (int i = 0; i < D_K / 4; i++) {
                    float4 kv = kr[i];
                    a0 = fmaf(q[i].x, kv.x, a0);
                    a1 = fmaf(q[i].y, kv.y, a1);
                    a2 = fmaf(q[i].z, kv.z, a2);
                    a3 = fmaf(q[i].w, kv.w, a3);
                }
                float sc = (a0 + a1) + (a2 + a3);
                sc *= scale;
                s[jj] = (kb + j <= row) ? sc : -INFINITY;
                smax = fmaxf(smax, s[jj]);
            }
            const float newm = fmaxf(m, smax);
            if (newm != -INFINITY) {
                const float corr = __expf(m - newm);
                m = newm;
                l *= corr;
#pragma unroll
                for (int i = 0; i < D_K / 4; i++) {
                    o[i].x *= corr; o[i].y *= corr; o[i].z *= corr; o[i].w *= corr;
                }
#pragma unroll
                for (int jj = 0; jj < CH; jj++) {
                    const float p = __expf(s[jj] - m);
                    l += p;
                    const float4* vr = (const float4*)Vs[jc + jj];
#pragma unroll
                    for (int i = 0; i < D_K / 4; i++) {
                        float4 vv = vr[i];
                        o[i].x = fmaf(p, vv.x, o[i].x);
                        o[i].y = fmaf(p, vv.y, o[i].y);
                        o[i].z = fmaf(p, vv.z, o[i].z);
                        o[i].w = fmaf(p, vv.w, o[i].w);
                    }
                }
            }
        }
        __syncthreads();
    }

    // epilogue: normalize and write split bf16 (hi/lo) into (B, L, D) layout
    const float inv = 1.0f / l;
    const int b = bh >> 4;
    const int h = bh & 15;
    const size_t base = ((size_t)b * SEQLEN + row) * D_MODEL + h * D_K;
#pragma unroll
    for (int i = 0; i < D_K / 4; i++) {
        float4 v = o[i];
        v.x *= inv; v.y *= inv; v.z *= inv; v.w *= inv;
        uint32_t l0, l1;
        const uint32_t h0 = split_pair(v.x, v.y, l0);
        const uint32_t h1 = split_pair(v.z, v.w, l1);
        *(uint2*)(g_atth + base + i * 4) = make_uint2(h0, h1);
        *(uint2*)(g_attl + base + i * 4) = make_uint2(l0, l1);
    }
}

// ---------------- launcher ----------------
extern "C" void kernel_launch(void* const* d_in, const int* in_sizes, int n_in,
                              void* d_out, int out_size)
{
    const float* Q  = (const float*)d_in[0];
    const float* K  = (const float*)d_in[1];
    const float* V  = (const float*)d_in[2];
    // d_in[3] = attn_mask (tril) — implemented implicitly as causal
    const float* Wq = (const float*)d_in[4];
    const float* bq = (const float*)d_in[5];
    const float* Wk = (const float*)d_in[6];
    const float* bk = (const float*)d_in[7];
    const float* Wv = (const float*)d_in[8];
    const float* bv = (const float*)d_in[9];
    const float* Wo = (const float*)d_in[10];
    const float* bo = (const float*)d_in[11];
    float* out = (float*)d_out;

    float *pq, *pk, *pv;
    __nv_bfloat16 *xqh, *xql, *xkh, *xkl, *xvh, *xvl;
    __nv_bfloat16 *wqh, *wql, *wkh, *wkl, *wvh, *wvl, *woh, *wol;
    __nv_bfloat16 *atth, *attl;
    cudaGetSymbolAddress((void**)&pq, g_q);
    cudaGetSymbolAddress((void**)&pk, g_k);
    cudaGetSymbolAddress((void**)&pv, g_v);
    cudaGetSymbolAddress((void**)&xqh, g_xqh); cudaGetSymbolAddress((void**)&xql, g_xql);
    cudaGetSymbolAddress((void**)&xkh, g_xkh); cudaGetSymbolAddress((void**)&xkl, g_xkl);
    cudaGetSymbolAddress((void**)&xvh, g_xvh); cudaGetSymbolAddress((void**)&xvl, g_xvl);
    cudaGetSymbolAddress((void**)&wqh, g_wqh); cudaGetSymbolAddress((void**)&wql, g_wql);
    cudaGetSymbolAddress((void**)&wkh, g_wkh); cudaGetSymbolAddress((void**)&wkl, g_wkl);
    cudaGetSymbolAddress((void**)&wvh, g_wvh); cudaGetSymbolAddress((void**)&wvl, g_wvl);
    cudaGetSymbolAddress((void**)&woh, g_woh); cudaGetSymbolAddress((void**)&wol, g_wol);
    cudaGetSymbolAddress((void**)&atth, g_atth); cudaGetSymbolAddress((void**)&attl, g_attl);

    cudaFuncSetAttribute(gemm_bf16_kernel<true>,
                         cudaFuncAttributeMaxDynamicSharedMemorySize, SM_TOT);
    cudaFuncSetAttribute(gemm_bf16_kernel<false>,
                         cudaFuncAttributeMaxDynamicSharedMemorySize, SM_TOT);

    // ---- pre-split inputs and weights ----
    const int nAct4 = M_ROWS * D_MODEL / 4;    // 2,097,152 -> 8192 blocks
    const int nW4   = D_MODEL * D_MODEL / 4;   // 262,144   -> 1024 blocks
    split_kernel<<<nAct4 / 256, 256>>>((const float4*)Q, xqh, xql);
    split_kernel<<<nAct4 / 256, 256>>>((const float4*)K, xkh, xkl);
    split_kernel<<<nAct4 / 256, 256>>>((const float4*)V, xvh, xvl);
    split_kernel<<<nW4 / 256, 256>>>((const float4*)Wq, wqh, wql);
    split_kernel<<<nW4 / 256, 256>>>((const float4*)Wk, wkh, wkl);
    split_kernel<<<nW4 / 256, 256>>>((const float4*)Wv, wvh, wvl);
    split_kernel<<<nW4 / 256, 256>>>((const float4*)Wo, woh, wol);

    dim3 ggrid(D_MODEL / GBN, M_ROWS / GBM);   // (8, 64)
    gemm_bf16_kernel<true><<<ggrid, 256, SM_TOT>>>(xqh, xql, wqh, wql, bq, pq);
    gemm_bf16_kernel<true><<<ggrid, 256, SM_TOT>>>(xkh, xkl, wkh, wkl, bk, pk);
    gemm_bf16_kernel<true><<<ggrid, 256, SM_TOT>>>(xvh, xvl, wvh, wvl, bv, pv);

    dim3 attn_grid(SEQLEN / QT, BATCH * N_HEADS); // (16, 64)
    flash_attn_kernel<<<attn_grid, QT>>>();

    gemm_bf16_kernel<false><<<ggrid, 256, SM_TOT>>>(atth, attl, woh, wol, bo, out);
}

// round 9
// speedup vs baseline: 3.3130x; 2.0946x over previous
#include <cuda_runtime.h>
#include <cuda_bf16.h>
#include <math.h>
#include <stdint.h>

// Problem constants
#define D_MODEL 1024
#define N_HEADS 16
#define D_K     64
#define BATCH   4
#define SEQLEN  2048
#define M_ROWS  (BATCH * SEQLEN)   // 8192

// ---------------- scratch (device globals; no allocs allowed) ----------------
// pre-split bf16 operands for projections
__device__ __nv_bfloat16 g_xqh[(size_t)M_ROWS * D_MODEL], g_xql[(size_t)M_ROWS * D_MODEL];
__device__ __nv_bfloat16 g_xkh[(size_t)M_ROWS * D_MODEL], g_xkl[(size_t)M_ROWS * D_MODEL];
__device__ __nv_bfloat16 g_xvh[(size_t)M_ROWS * D_MODEL], g_xvl[(size_t)M_ROWS * D_MODEL];
__device__ __nv_bfloat16 g_wqh[(size_t)D_MODEL * D_MODEL], g_wql[(size_t)D_MODEL * D_MODEL];
__device__ __nv_bfloat16 g_wkh[(size_t)D_MODEL * D_MODEL], g_wkl[(size_t)D_MODEL * D_MODEL];
__device__ __nv_bfloat16 g_wvh[(size_t)D_MODEL * D_MODEL], g_wvl[(size_t)D_MODEL * D_MODEL];
__device__ __nv_bfloat16 g_woh[(size_t)D_MODEL * D_MODEL], g_wol[(size_t)D_MODEL * D_MODEL];
// projected q/k/v in split bf16, (B*H, L, D_K) head-major; q pre-scaled by 1/8
__device__ __nv_bfloat16 g_qh[(size_t)BATCH * N_HEADS * SEQLEN * D_K];
__device__ __nv_bfloat16 g_ql[(size_t)BATCH * N_HEADS * SEQLEN * D_K];
__device__ __nv_bfloat16 g_kh[(size_t)BATCH * N_HEADS * SEQLEN * D_K];
__device__ __nv_bfloat16 g_kl[(size_t)BATCH * N_HEADS * SEQLEN * D_K];
__device__ __nv_bfloat16 g_vh[(size_t)BATCH * N_HEADS * SEQLEN * D_K];
__device__ __nv_bfloat16 g_vl[(size_t)BATCH * N_HEADS * SEQLEN * D_K];
// attention output, split bf16, (B, L, D)
__device__ __nv_bfloat16 g_atth[(size_t)M_ROWS * D_MODEL], g_attl[(size_t)M_ROWS * D_MODEL];

// ======================= helpers =======================
__device__ __forceinline__ uint32_t smem_u32(const void* p) {
    uint32_t a;
    asm("{ .reg .u64 t; cvta.to.shared.u64 t, %1; cvt.u32.u64 %0, t; }"
        : "=r"(a) : "l"(p));
    return a;
}

__device__ __forceinline__ void cp16(uint32_t dst, const void* src) {
    asm volatile("cp.async.cg.shared.global [%0], [%1], 16;" :: "r"(dst), "l"(src));
}
__device__ __forceinline__ void cp_commit() {
    asm volatile("cp.async.commit_group;" ::: "memory");
}
__device__ __forceinline__ void cp_wait0() {
    asm volatile("cp.async.wait_group 0;" ::: "memory");
}

__device__ __forceinline__ void ldmx4(uint32_t* r, uint32_t addr) {
    asm volatile("ldmatrix.sync.aligned.m8n8.x4.shared.b16 {%0,%1,%2,%3}, [%4];"
                 : "=r"(r[0]), "=r"(r[1]), "=r"(r[2]), "=r"(r[3]) : "r"(addr));
}
__device__ __forceinline__ void ldmx4t(uint32_t* r, uint32_t addr) {
    asm volatile("ldmatrix.sync.aligned.m8n8.x4.trans.shared.b16 {%0,%1,%2,%3}, [%4];"
                 : "=r"(r[0]), "=r"(r[1]), "=r"(r[2]), "=r"(r[3]) : "r"(addr));
}

__device__ __forceinline__ void mma_bf16(float* c, const uint32_t* a, const uint32_t* b) {
    asm volatile(
        "mma.sync.aligned.m16n8k16.row.col.f32.bf16.bf16.f32 "
        "{%0,%1,%2,%3}, {%4,%5,%6,%7}, {%8,%9}, {%0,%1,%2,%3};"
        : "+f"(c[0]), "+f"(c[1]), "+f"(c[2]), "+f"(c[3])
        : "r"(a[0]), "r"(a[1]), "r"(a[2]), "r"(a[3]), "r"(b[0]), "r"(b[1]));
}

// split fp32 -> bf16 hi + bf16 lo (packed pairs)
__device__ __forceinline__ uint32_t split_pair(float a, float b, uint32_t& lo_out) {
    __nv_bfloat16 ha = __float2bfloat16(a);
    __nv_bfloat16 hb = __float2bfloat16(b);
    float ra = a - __bfloat162float(ha);
    float rb = b - __bfloat162float(hb);
    __nv_bfloat16 la = __float2bfloat16(ra);
    __nv_bfloat16 lb = __float2bfloat16(rb);
    lo_out = (uint32_t)__bfloat16_as_ushort(la) | ((uint32_t)__bfloat16_as_ushort(lb) << 16);
    return (uint32_t)__bfloat16_as_ushort(ha) | ((uint32_t)__bfloat16_as_ushort(hb) << 16);
}

// ---------------- split pass: fp32 -> (hi, lo) bf16 ----------------
__global__ __launch_bounds__(256) void split_kernel(
    const float4* __restrict__ src, __nv_bfloat16* __restrict__ hi,
    __nv_bfloat16* __restrict__ lo)
{
    const int i = blockIdx.x * 256 + threadIdx.x;
    const float4 f = src[i];
    uint32_t l0, l1;
    const uint32_t h0 = split_pair(f.x, f.y, l0);
    const uint32_t h1 = split_pair(f.z, f.w, l1);
    ((uint2*)hi)[i] = make_uint2(h0, h1);
    ((uint2*)lo)[i] = make_uint2(l0, l1);
}

// ============== mma.sync GEMM: C = (A @ W^T + bias) * scale ==============
// A_hi/lo: [M,1024] bf16, W_hi/lo: [1024,1024] bf16, all K-contiguous.
// CTA tile 128x128, 8 warps (4 M x 2 N), warp tile 32x64, BK=32, double-buffered.
// REMAP=1: write split bf16 to (B*H, L, DK) layout; REMAP=0: fp32 [M,N].
#define GBM 128
#define GBN 128
#define GBK 32
#define NKT (D_MODEL / GBK)          // 32
#define ROWB 80                      // smem row stride (32 bf16 = 64B + 16B pad)
#define SBUF (128 * ROWB)            // 10240 B per tile array
#define SM_TOT (2 * 4 * SBUF)        // 81920 B

template <int REMAP>
__global__ __launch_bounds__(256, 2) void gemm_bf16_kernel(
    const __nv_bfloat16* __restrict__ Ah, const __nv_bfloat16* __restrict__ Al,
    const __nv_bfloat16* __restrict__ Wh, const __nv_bfloat16* __restrict__ Wl,
    const float* __restrict__ bias, float* __restrict__ C,
    __nv_bfloat16* __restrict__ Ch, __nv_bfloat16* __restrict__ Cl, float scale)
{
    extern __shared__ __align__(16) char smem[];
    const uint32_t sb = smem_u32(smem);

    const int tid  = threadIdx.x;
    const int wid  = tid >> 5;
    const int lane = tid & 31;
    const int warp_m = wid & 3;
    const int warp_n = wid >> 2;

    const int aRow0 = blockIdx.y * GBM;
    const int wRow0 = blockIdx.x * GBN;

    const int g = lane >> 3;
    const int ra = warp_m * 32 + (g & 1) * 8 + (lane & 7);
    const int ka = (g >> 1) * 16;
    const int rb = warp_n * 64 + (g >> 1) * 8 + (lane & 7);
    const int kb = (g & 1) * 16;

    float acc[2][8][4];
#pragma unroll
    for (int i = 0; i < 2; i++)
#pragma unroll
        for (int j = 0; j < 8; j++)
#pragma unroll
            for (int k = 0; k < 4; k++) acc[i][j][k] = 0.0f;

    auto load_tiles = [&](uint32_t bufbase, int kt) {
#pragma unroll
        for (int u = 0; u < 2; u++) {
            const int c   = u * 256 + tid;
            const int row = c >> 2;
            const int c4  = c & 3;
            const size_t aoff = (size_t)(aRow0 + row) * D_MODEL + kt * GBK + c4 * 8;
            const size_t woff = (size_t)(wRow0 + row) * D_MODEL + kt * GBK + c4 * 8;
            const uint32_t d = (uint32_t)(row * ROWB + c4 * 16);
            cp16(bufbase + 0 * SBUF + d, Ah + aoff);
            cp16(bufbase + 1 * SBUF + d, Al + aoff);
            cp16(bufbase + 2 * SBUF + d, Wh + woff);
            cp16(bufbase + 3 * SBUF + d, Wl + woff);
        }
    };

    load_tiles(sb, 0);
    cp_commit();

    for (int kt = 0; kt < NKT; kt++) {
        cp_wait0();
        __syncthreads();

        if (kt + 1 < NKT) {
            load_tiles(sb + ((kt + 1) & 1) * 4 * SBUF, kt + 1);
            cp_commit();
        }

        const uint32_t base = sb + (kt & 1) * 4 * SBUF;
        const uint32_t bAh = base, bAl = base + SBUF, bWh = base + 2 * SBUF, bWl = base + 3 * SBUF;

#pragma unroll
        for (int ks = 0; ks < 2; ks++) {
            uint32_t ah[2][4], al[2][4];
#pragma unroll
            for (int mc = 0; mc < 2; mc++) {
                const uint32_t arow = (uint32_t)((ra + mc * 16) * ROWB + ks * 32 + ka);
                ldmx4(ah[mc], bAh + arow);
                ldmx4(al[mc], bAl + arow);
            }
#pragma unroll
            for (int ncp = 0; ncp < 4; ncp++) {
                uint32_t b[4];
                ldmx4(b, bWh + (uint32_t)((rb + ncp * 16) * ROWB + ks * 32 + kb));
#pragma unroll
                for (int mc = 0; mc < 2; mc++) {
                    mma_bf16(acc[mc][ncp * 2 + 0], ah[mc], b);
                    mma_bf16(acc[mc][ncp * 2 + 1], ah[mc], b + 2);
                    mma_bf16(acc[mc][ncp * 2 + 0], al[mc], b);
                    mma_bf16(acc[mc][ncp * 2 + 1], al[mc], b + 2);
                }
            }
#pragma unroll
            for (int ncp = 0; ncp < 4; ncp++) {
                uint32_t b[4];
                ldmx4(b, bWl + (uint32_t)((rb + ncp * 16) * ROWB + ks * 32 + kb));
#pragma unroll
                for (int mc = 0; mc < 2; mc++) {
                    mma_bf16(acc[mc][ncp * 2 + 0], ah[mc], b);
                    mma_bf16(acc[mc][ncp * 2 + 1], ah[mc], b + 2);
                }
            }
        }
        __syncthreads();
    }

    // ---- epilogue ----
    const int r0 = blockIdx.y * GBM + warp_m * 32 + (lane >> 2);
    const int c0 = blockIdx.x * GBN + warp_n * 64 + (lane & 3) * 2;
#pragma unroll
    for (int mc = 0; mc < 2; mc++) {
#pragma unroll
        for (int nc = 0; nc < 8; nc++) {
            const int n = c0 + nc * 8;
            const float2 bv = *(const float2*)(bias + n);
#pragma unroll
            for (int h2 = 0; h2 < 2; h2++) {
                const int m = r0 + mc * 16 + h2 * 8;
                float vx = (acc[mc][nc][h2 * 2 + 0] + bv.x) * scale;
                float vy = (acc[mc][nc][h2 * 2 + 1] + bv.y) * scale;
                if (REMAP) {
                    const int b  = m >> 11;
                    const int l  = m & 2047;
                    const int hd = n >> 6;
                    const int dk = n & 63;
                    const size_t idx = ((((size_t)b * N_HEADS + hd) * SEQLEN) + l) * D_K + dk;
                    uint32_t lo;
                    const uint32_t hi = split_pair(vx, vy, lo);
                    *(uint32_t*)(Ch + idx) = hi;
                    *(uint32_t*)(Cl + idx) = lo;
                } else {
                    *(float2*)(C + (size_t)m * D_MODEL + n) = make_float2(vx, vy);
                }
            }
        }
    }
}

// ============== tensor-core flash attention (split bf16, causal) ==============
// CTA: 128 threads (4 warps), Q tile 64 rows (16/warp), KV tiles 64.
#define AROWB 144                     // 64 bf16 (128B) + 16B pad
#define ATILE (64 * AROWB)            // 9216 B
#define SQH 0
#define SQL (1 * ATILE)
#define SKH (2 * ATILE)
#define SKL (3 * ATILE)
#define SVH (4 * ATILE)
#define SVL (5 * ATILE)
#define ASM_TOT (6 * ATILE)           // 55296 B

__global__ __launch_bounds__(128, 2) void flash_mma_kernel()
{
    extern __shared__ __align__(16) char smem[];
    const uint32_t sb = smem_u32(smem);

    const int tid  = threadIdx.x;
    const int wid  = tid >> 5;           // 0..3, warp m-base = wid*16
    const int lane = tid & 31;
    const int bh   = blockIdx.y;         // 0..63
    const int qt   = blockIdx.x;         // 0..31
    const int q0   = qt * 64;

    const size_t headbase = (size_t)bh * SEQLEN * D_K;

    // ---- load Q tile (hi/lo) ----
    {
        const __nv_bfloat16* qh = g_qh + headbase + (size_t)q0 * D_K;
        const __nv_bfloat16* ql = g_ql + headbase + (size_t)q0 * D_K;
#pragma unroll
        for (int u = 0; u < 4; u++) {
            const int c   = u * 128 + tid;  // 0..511
            const int row = c >> 3;
            const int cc  = c & 7;
            const uint32_t d = (uint32_t)(row * AROWB + cc * 16);
            cp16(sb + SQH + d, qh + row * D_K + cc * 8);
            cp16(sb + SQL + d, ql + row * D_K + cc * 8);
        }
        cp_commit();
        cp_wait0();
        __syncthreads();
    }

    // ---- Q fragments (A-layout, m16k16 per kstep) ----
    const int g  = lane >> 3;
    const int ra = wid * 16 + (g & 1) * 8 + (lane & 7);
    const int ka = (g >> 1) * 16;
    uint32_t qfh[4][4], qfl[4][4];
#pragma unroll
    for (int ks = 0; ks < 4; ks++) {
        ldmx4(qfh[ks], sb + SQH + (uint32_t)(ra * AROWB + ks * 32 + ka));
        ldmx4(qfl[ks], sb + SQL + (uint32_t)(ra * AROWB + ks * 32 + ka));
    }

    // K B-frag addressing (non-trans, [kv][d] storage, k = d contiguous)
    const int rbk = (g >> 1) * 8 + (lane & 7);
    const int kbk = (g & 1) * 16;
    // V B-frag addressing (trans, [kv][d] storage -> [d][kv] fragment)
    const int rv = (g & 1) * 8 + (lane & 7);
    const int cv = (g >> 1) * 16;

    float O[8][4];
#pragma unroll
    for (int j = 0; j < 8; j++)
#pragma unroll
        for (int k = 0; k < 4; k++) O[j][k] = 0.0f;
    float mrow0 = -INFINITY, mrow1 = -INFINITY;
    float lrow0 = 0.0f, lrow1 = 0.0f;

    const __nv_bfloat16* khp = g_kh + headbase;
    const __nv_bfloat16* klp = g_kl + headbase;
    const __nv_bfloat16* vhp = g_vh + headbase;
    const __nv_bfloat16* vlp = g_vl + headbase;

    for (int kvt = 0; kvt <= qt; kvt++) {
        const int kv0 = kvt * 64;
        // ---- load K/V tiles (hi/lo) ----
#pragma unroll
        for (int u = 0; u < 4; u++) {
            const int c   = u * 128 + tid;
            const int row = c >> 3;
            const int cc  = c & 7;
            const size_t off = (size_t)(kv0 + row) * D_K + cc * 8;
            const uint32_t d = (uint32_t)(row * AROWB + cc * 16);
            cp16(sb + SKH + d, khp + off);
            cp16(sb + SKL + d, klp + off);
            cp16(sb + SVH + d, vhp + off);
            cp16(sb + SVL + d, vlp + off);
        }
        cp_commit();
        cp_wait0();
        __syncthreads();

        // ---- S = Q K^T (3 split terms) ----
        float S[8][4];
#pragma unroll
        for (int j = 0; j < 8; j++)
#pragma unroll
            for (int k = 0; k < 4; k++) S[j][k] = 0.0f;

#pragma unroll
        for (int ks = 0; ks < 4; ks++) {
#pragma unroll
            for (int np = 0; np < 4; np++) {
                uint32_t b[4];
                const uint32_t krow = (uint32_t)((np * 16 + rbk) * AROWB + ks * 32 + kbk);
                ldmx4(b, sb + SKH + krow);
                mma_bf16(S[np * 2 + 0], qfh[ks], b);
                mma_bf16(S[np * 2 + 1], qfh[ks], b + 2);
                mma_bf16(S[np * 2 + 0], qfl[ks], b);
                mma_bf16(S[np * 2 + 1], qfl[ks], b + 2);
                ldmx4(b, sb + SKL + krow);
                mma_bf16(S[np * 2 + 0], qfh[ks], b);
                mma_bf16(S[np * 2 + 1], qfh[ks], b + 2);
            }
        }

        // ---- causal mask (diagonal tile only) ----
        if (kvt == qt) {
            const int r0g = q0 + wid * 16 + (lane >> 2);
#pragma unroll
            for (int nc = 0; nc < 8; nc++) {
                const int colb = kv0 + nc * 8 + (lane & 3) * 2;
#pragma unroll
                for (int c = 0; c < 4; c++) {
                    const int col = colb + (c & 1);
                    const int rowg = r0g + ((c >= 2) ? 8 : 0);
                    if (col > rowg) S[nc][c] = -INFINITY;
                }
            }
        }

        // ---- online softmax ----
        float mt0 = -INFINITY, mt1 = -INFINITY;
#pragma unroll
        for (int nc = 0; nc < 8; nc++) {
            mt0 = fmaxf(mt0, fmaxf(S[nc][0], S[nc][1]));
            mt1 = fmaxf(mt1, fmaxf(S[nc][2], S[nc][3]));
        }
        mt0 = fmaxf(mt0, __shfl_xor_sync(0xffffffffu, mt0, 1));
        mt0 = fmaxf(mt0, __shfl_xor_sync(0xffffffffu, mt0, 2));
        mt1 = fmaxf(mt1, __shfl_xor_sync(0xffffffffu, mt1, 1));
        mt1 = fmaxf(mt1, __shfl_xor_sync(0xffffffffu, mt1, 2));

        const float mn0 = fmaxf(mrow0, mt0);
        const float mn1 = fmaxf(mrow1, mt1);
        const float corr0 = __expf(mrow0 - mn0);
        const float corr1 = __expf(mrow1 - mn1);
        mrow0 = mn0; mrow1 = mn1;

        float rs0 = 0.0f, rs1 = 0.0f;
#pragma unroll
        for (int nc = 0; nc < 8; nc++) {
            S[nc][0] = __expf(S[nc][0] - mn0); rs0 += S[nc][0];
            S[nc][1] = __expf(S[nc][1] - mn0); rs0 += S[nc][1];
            S[nc][2] = __expf(S[nc][2] - mn1); rs1 += S[nc][2];
            S[nc][3] = __expf(S[nc][3] - mn1); rs1 += S[nc][3];
        }
        rs0 += __shfl_xor_sync(0xffffffffu, rs0, 1);
        rs0 += __shfl_xor_sync(0xffffffffu, rs0, 2);
        rs1 += __shfl_xor_sync(0xffffffffu, rs1, 1);
        rs1 += __shfl_xor_sync(0xffffffffu, rs1, 2);
        lrow0 = lrow0 * corr0 + rs0;
        lrow1 = lrow1 * corr1 + rs1;

#pragma unroll
        for (int nc = 0; nc < 8; nc++) {
            O[nc][0] *= corr0; O[nc][1] *= corr0;
            O[nc][2] *= corr1; O[nc][3] *= corr1;
        }

        // ---- O += P V (3 split terms) ----
#pragma unroll
        for (int ks = 0; ks < 4; ks++) {
            uint32_t ph[4], pl[4];
            ph[0] = split_pair(S[2 * ks][0],     S[2 * ks][1],     pl[0]);
            ph[1] = split_pair(S[2 * ks][2],     S[2 * ks][3],     pl[1]);
            ph[2] = split_pair(S[2 * ks + 1][0], S[2 * ks + 1][1], pl[2]);
            ph[3] = split_pair(S[2 * ks + 1][2], S[2 * ks + 1][3], pl[3]);
#pragma unroll
            for (int np = 0; np < 4; np++) {
                uint32_t bv[4];
                const uint32_t vrow = (uint32_t)((ks * 16 + rv) * AROWB + np * 32 + cv);
                ldmx4t(bv, sb + SVH + vrow);
                mma_bf16(O[np * 2 + 0], ph, bv);
                mma_bf16(O[np * 2 + 1], ph, bv + 2);
                mma_bf16(O[np * 2 + 0], pl, bv);
                mma_bf16(O[np * 2 + 1], pl, bv + 2);
                ldmx4t(bv, sb + SVL + vrow);
                mma_bf16(O[np * 2 + 0], ph, bv);
                mma_bf16(O[np * 2 + 1], ph, bv + 2);
            }
        }
        __syncthreads();   // before next tile overwrites K/V
    }

    // ---- epilogue: normalize, split, write (B, L, D) ----
    const float inv0 = 1.0f / lrow0;
    const float inv1 = 1.0f / lrow1;
    const int b = bh >> 4;
    const int h = bh & 15;
    const int row0 = q0 + wid * 16 + (lane >> 2);
    const int colb = (lane & 3) * 2;
#pragma unroll
    for (int nc = 0; nc < 8; nc++) {
        const int d = colb + nc * 8;
        const size_t i0 = (((size_t)b * SEQLEN + row0) * D_MODEL) + h * D_K + d;
        const size_t i1 = (((size_t)b * SEQLEN + row0 + 8) * D_MODEL) + h * D_K + d;
        uint32_t lo;
        uint32_t hi = split_pair(O[nc][0] * inv0, O[nc][1] * inv0, lo);
        *(uint32_t*)(g_atth + i0) = hi;
        *(uint32_t*)(g_attl + i0) = lo;
        hi = split_pair(O[nc][2] * inv1, O[nc][3] * inv1, lo);
        *(uint32_t*)(g_atth + i1) = hi;
        *(uint32_t*)(g_attl + i1) = lo;
    }
}

// ---------------- launcher ----------------
extern "C" void kernel_launch(void* const* d_in, const int* in_sizes, int n_in,
                              void* d_out, int out_size)
{
    const float* Q  = (const float*)d_in[0];
    const float* K  = (const float*)d_in[1];
    const float* V  = (const float*)d_in[2];
    // d_in[3] = attn_mask (tril) — implemented implicitly as causal
    const float* Wq = (const float*)d_in[4];
    const float* bq = (const float*)d_in[5];
    const float* Wk = (const float*)d_in[6];
    const float* bk = (const float*)d_in[7];
    const float* Wv = (const float*)d_in[8];
    const float* bv = (const float*)d_in[9];
    const float* Wo = (const float*)d_in[10];
    const float* bo = (const float*)d_in[11];
    float* out = (float*)d_out;

    __nv_bfloat16 *xqh, *xql, *xkh, *xkl, *xvh, *xvl;
    __nv_bfloat16 *wqh, *wql, *wkh, *wkl, *wvh, *wvl, *woh, *wol;
    __nv_bfloat16 *qh, *ql, *kh, *kl, *vh, *vl, *atth, *attl;
    cudaGetSymbolAddress((void**)&xqh, g_xqh); cudaGetSymbolAddress((void**)&xql, g_xql);
    cudaGetSymbolAddress((void**)&xkh, g_xkh); cudaGetSymbolAddress((void**)&xkl, g_xkl);
    cudaGetSymbolAddress((void**)&xvh, g_xvh); cudaGetSymbolAddress((void**)&xvl, g_xvl);
    cudaGetSymbolAddress((void**)&wqh, g_wqh); cudaGetSymbolAddress((void**)&wql, g_wql);
    cudaGetSymbolAddress((void**)&wkh, g_wkh); cudaGetSymbolAddress((void**)&wkl, g_wkl);
    cudaGetSymbolAddress((void**)&wvh, g_wvh); cudaGetSymbolAddress((void**)&wvl, g_wvl);
    cudaGetSymbolAddress((void**)&woh, g_woh); cudaGetSymbolAddress((void**)&wol, g_wol);
    cudaGetSymbolAddress((void**)&qh, g_qh);   cudaGetSymbolAddress((void**)&ql, g_ql);
    cudaGetSymbolAddress((void**)&kh, g_kh);   cudaGetSymbolAddress((void**)&kl, g_kl);
    cudaGetSymbolAddress((void**)&vh, g_vh);   cudaGetSymbolAddress((void**)&vl, g_vl);
    cudaGetSymbolAddress((void**)&atth, g_atth); cudaGetSymbolAddress((void**)&attl, g_attl);

    cudaFuncSetAttribute(gemm_bf16_kernel<1>,
                         cudaFuncAttributeMaxDynamicSharedMemorySize, SM_TOT);
    cudaFuncSetAttribute(gemm_bf16_kernel<0>,
                         cudaFuncAttributeMaxDynamicSharedMemorySize, SM_TOT);
    cudaFuncSetAttribute(flash_mma_kernel,
                         cudaFuncAttributeMaxDynamicSharedMemorySize, ASM_TOT);

    // ---- pre-split inputs and weights ----
    const int nAct4 = M_ROWS * D_MODEL / 4;
    const int nW4   = D_MODEL * D_MODEL / 4;
    split_kernel<<<nAct4 / 256, 256>>>((const float4*)Q, xqh, xql);
    split_kernel<<<nAct4 / 256, 256>>>((const float4*)K, xkh, xkl);
    split_kernel<<<nAct4 / 256, 256>>>((const float4*)V, xvh, xvl);
    split_kernel<<<nW4 / 256, 256>>>((const float4*)Wq, wqh, wql);
    split_kernel<<<nW4 / 256, 256>>>((const float4*)Wk, wkh, wkl);
    split_kernel<<<nW4 / 256, 256>>>((const float4*)Wv, wvh, wvl);
    split_kernel<<<nW4 / 256, 256>>>((const float4*)Wo, woh, wol);

    dim3 ggrid(D_MODEL / GBN, M_ROWS / GBM);   // (8, 64)
    // q scaled by 1/sqrt(d_k) = 0.125 at projection time
    gemm_bf16_kernel<1><<<ggrid, 256, SM_TOT>>>(xqh, xql, wqh, wql, bq, nullptr, qh, ql, 0.125f);
    gemm_bf16_kernel<1><<<ggrid, 256, SM_TOT>>>(xkh, xkl, wkh, wkl, bk, nullptr, kh, kl, 1.0f);
    gemm_bf16_kernel<1><<<ggrid, 256, SM_TOT>>>(xvh, xvl, wvh, wvl, bv, nullptr, vh, vl, 1.0f);

    dim3 attn_grid(SEQLEN / 64, BATCH * N_HEADS); // (32, 64)
    flash_mma_kernel<<<attn_grid, 128, ASM_TOT>>>();

    gemm_bf16_kernel<0><<<ggrid, 256, SM_TOT>>>(atth, attl, woh, wol, bo, out, nullptr, nullptr, 1.0f);
}